// round 3
// baseline (speedup 1.0000x reference)
#include <cuda_runtime.h>

#define NN 50000
#define EE 500000
#define HD 128
#define NLAY 4
#define NG 64

// ---------------- scratch (device globals; no allocation in kernel_launch) ----
__device__ __align__(16) float d_h[NN * HD];
__device__ __align__(16) float d_P1[NN * HD];
__device__ __align__(16) float d_P2[NN * HD];
__device__ __align__(16) float d_Yagg[NN * HD];
__device__ __align__(16) float d_T[NN * HD];
__device__ __align__(16) float d_dist[EE];
__device__ __align__(16) float d_degf[NN];
__device__ __align__(16) float d_W2U[NLAY * HD * HD];
__device__ __align__(16) float d_cvec[NLAY * HD];
__device__ __align__(16) float d_pooled[NG * HD];
__device__ __align__(16) float d_cnt[NG];

// ---------------- f32x2 packed helpers ---------------------------------------
__device__ __forceinline__ unsigned long long pk2(float lo, float hi) {
    unsigned long long r;
    asm("mov.b64 %0, {%1,%2};" : "=l"(r) : "f"(lo), "f"(hi));
    return r;
}
__device__ __forceinline__ void upk2(unsigned long long v, float& lo, float& hi) {
    asm("mov.b64 {%0,%1}, %2;" : "=f"(lo), "=f"(hi) : "l"(v));
}
__device__ __forceinline__ unsigned long long fma2(unsigned long long a,
                                                   unsigned long long b,
                                                   unsigned long long c) {
    unsigned long long d;
    asm("fma.rn.f32x2 %0, %1, %2, %3;" : "=l"(d) : "l"(a), "l"(b), "l"(c));
    return d;
}

// ---------------- small kernels ----------------------------------------------
__global__ void zero_k(float* __restrict__ p, int n) {
    int i = blockIdx.x * blockDim.x + threadIdx.x;
    if (i < n) p[i] = 0.0f;
}

__global__ void prep_edges(const int* __restrict__ ei,
                           const float* __restrict__ pos,
                           float* __restrict__ dist,
                           float* __restrict__ degf) {
    int e = blockIdx.x * blockDim.x + threadIdx.x;
    if (e >= EE) return;
    int s = ei[e];
    int t = ei[EE + e];
    float dx = pos[t * 3 + 0] - pos[s * 3 + 0];
    float dy = pos[t * 3 + 1] - pos[s * 3 + 1];
    float dz = pos[t * 3 + 2] - pos[s * 3 + 2];
    dist[e] = sqrtf(dx * dx + dy * dy + dz * dz);
    atomicAdd(&degf[t], 1.0f);
}

// h = x @ enc_w + enc_b   (K=15)
__global__ void encoder_k(const float* __restrict__ x,
                          const float* __restrict__ w,
                          const float* __restrict__ b,
                          float* __restrict__ h) {
    __shared__ float ws[15 * HD];
    __shared__ float xs[16 * 15];
    __shared__ float bs[HD];
    int c = threadIdx.x;
    for (int i = c; i < 15 * HD; i += HD) ws[i] = w[i];
    bs[c] = b[c];
    int n0 = blockIdx.x * 16;
    for (int i = c; i < 16 * 15; i += HD) {
        int nn = i / 15, kk = i % 15;
        int g = n0 + nn;
        xs[i] = (g < NN) ? x[g * 15 + kk] : 0.0f;
    }
    __syncthreads();
    for (int r = 0; r < 16; r++) {
        int g = n0 + r;
        if (g >= NN) break;
        float acc = bs[c];
#pragma unroll
        for (int k = 0; k < 15; k++) acc += xs[r * 15 + k] * ws[k * HD + c];
        h[g * HD + c] = acc;
    }
}

// W2U[l] = msg_w2[l] @ U1b[l];  cvec[l] = msg_b2[l] @ U1b[l]
__global__ void build_w2u(const float* __restrict__ msg_w2,
                          const float* __restrict__ msg_b2,
                          const float* __restrict__ upd_w1,
                          float* __restrict__ W2U,
                          float* __restrict__ cvec) {
    int l = blockIdx.y, k = blockIdx.x, c = threadIdx.x;
    const float* u1b = upd_w1 + l * 256 * HD + 128 * HD;
    if (k < HD) {
        const float* wrow = msg_w2 + (l * HD + k) * HD;
        float acc = 0.0f;
        for (int j = 0; j < HD; j++) acc += wrow[j] * u1b[j * HD + c];
        W2U[(l * HD + k) * HD + c] = acc;
    } else {
        const float* brow = msg_b2 + l * HD;
        float acc = 0.0f;
        for (int j = 0; j < HD; j++) acc += brow[j] * u1b[j * HD + c];
        cvec[l * HD + c] = acc;
    }
}

// per-edge: y = relu(P1[dst] + P2[src] + dist*w1c); Yagg[dst] += y (scalar red)
__global__ void edge_k(const int* __restrict__ ei,
                       const float* __restrict__ dist,
                       const float* __restrict__ P1,
                       const float* __restrict__ P2,
                       const float* __restrict__ w1c,
                       float* __restrict__ Yagg) {
    int e = blockIdx.x * 8 + (threadIdx.x >> 5);
    int lane = threadIdx.x & 31;
    if (e >= EE) return;
    int src = ei[e];
    int dst = ei[EE + e];
    float dd = dist[e];
    const float4 a = *(const float4*)&P1[dst * HD + lane * 4];
    const float4 b = *(const float4*)&P2[src * HD + lane * 4];
    const float4 c = *(const float4*)&w1c[lane * 4];
    float y0 = fmaxf(a.x + b.x + dd * c.x, 0.0f);
    float y1 = fmaxf(a.y + b.y + dd * c.y, 0.0f);
    float y2 = fmaxf(a.z + b.z + dd * c.z, 0.0f);
    float y3 = fmaxf(a.w + b.w + dd * c.w, 0.0f);
    float* p = &Yagg[dst * HD + lane * 4];
    atomicAdd(p + 0, y0);
    atomicAdd(p + 1, y1);
    atomicAdd(p + 2, y2);
    atomicAdd(p + 3, y3);
}

// ---------------- main GEMM (tall-skinny, f32x2) ------------------------------
// Block: 512 thr = 16 warps; tile = 128 rows x 128 cols; warp -> 8 rows, lane -> 4 cols.
__device__ __forceinline__ void load_tile_A(float* As, const float* __restrict__ A,
                                            int rowbase, int tid, int n) {
    const float4* av = (const float4*)A;
    float4* asv = (float4*)As;
#pragma unroll
    for (int i = 0; i < 8; i++) {
        int idx = tid + i * 512;           // 0..4095
        int r = idx >> 5;
        int grow = rowbase + r;
        int cr = (grow < n) ? grow : (n - 1);
        asv[idx] = av[cr * 32 + (idx & 31)];
    }
}

__device__ __forceinline__ void gemm_compute(const float* As, const float* Bs,
                                             unsigned long long acc0[8],
                                             unsigned long long acc1[8],
                                             int warp, int lane) {
#pragma unroll 2
    for (int k0 = 0; k0 < HD; k0 += 4) {
        float4 avv[8];
#pragma unroll
        for (int r = 0; r < 8; r++)
            avv[r] = *(const float4*)&As[(warp * 8 + r) * HD + k0];
#pragma unroll
        for (int kk = 0; kk < 4; kk++) {
            const unsigned long long* bp =
                (const unsigned long long*)&Bs[(k0 + kk) * HD + lane * 4];
            unsigned long long b01 = bp[0];
            unsigned long long b23 = bp[1];
#pragma unroll
            for (int r = 0; r < 8; r++) {
                float a = (&avv[r].x)[kk];
                unsigned long long a2 = pk2(a, a);
                acc0[r] = fma2(a2, b01, acc0[r]);
                acc1[r] = fma2(a2, b23, acc1[r]);
            }
        }
    }
}

// EPI: 0 = +bias, 1 = plain, 2 = +deg*cvec+bias, relu, 3 = +bias, LN, relu, (+residual)
template <int EPI, bool TWOA>
__global__ void __launch_bounds__(512) gemm_k(
    const float* __restrict__ A0, const float* __restrict__ A1,
    const float* __restrict__ B0, const float* __restrict__ B1,
    const float* __restrict__ bias,
    const float* __restrict__ degf, const float* __restrict__ cvec,
    const float* __restrict__ lng, const float* __restrict__ lnb,
    int addres, float* __restrict__ Out, int n) {
    extern __shared__ float sm[];
    const int KB = TWOA ? 256 : 128;
    float* Bs = sm;
    float* As = sm + KB * HD;
    int tid = threadIdx.x;

    {   // load B (weights) into smem
        const float4* bv0 = (const float4*)B0;
        float4* bs = (float4*)Bs;
#pragma unroll
        for (int i = 0; i < 8; i++) bs[tid + i * 512] = bv0[tid + i * 512];
        if (TWOA) {
            const float4* bv1 = (const float4*)B1;
#pragma unroll
            for (int i = 0; i < 8; i++) bs[4096 + tid + i * 512] = bv1[tid + i * 512];
        }
    }
    int rowbase = blockIdx.x * 128;
    load_tile_A(As, A0, rowbase, tid, n);
    __syncthreads();

    unsigned long long acc0[8], acc1[8];
#pragma unroll
    for (int r = 0; r < 8; r++) { acc0[r] = 0ULL; acc1[r] = 0ULL; }

    int warp = tid >> 5, lane = tid & 31;
    gemm_compute(As, Bs, acc0, acc1, warp, lane);
    if (TWOA) {
        __syncthreads();
        load_tile_A(As, A1, rowbase, tid, n);
        __syncthreads();
        gemm_compute(As, Bs + 128 * HD, acc0, acc1, warp, lane);
    }

    int col = lane * 4;
    int rb = rowbase + warp * 8;
#pragma unroll
    for (int r = 0; r < 8; r++) {
        int grow = rb + r;
        float o0, o1, o2, o3;
        upk2(acc0[r], o0, o1);
        upk2(acc1[r], o2, o3);
        if (EPI == 0) {
            o0 += bias[col + 0]; o1 += bias[col + 1];
            o2 += bias[col + 2]; o3 += bias[col + 3];
        }
        if (EPI == 2) {
            float dg = degf[(grow < n) ? grow : 0];
            o0 = fmaxf(o0 + dg * cvec[col + 0] + bias[col + 0], 0.0f);
            o1 = fmaxf(o1 + dg * cvec[col + 1] + bias[col + 1], 0.0f);
            o2 = fmaxf(o2 + dg * cvec[col + 2] + bias[col + 2], 0.0f);
            o3 = fmaxf(o3 + dg * cvec[col + 3] + bias[col + 3], 0.0f);
        }
        if (EPI == 3) {
            o0 += bias[col + 0]; o1 += bias[col + 1];
            o2 += bias[col + 2]; o3 += bias[col + 3];
            float s = o0 + o1 + o2 + o3;
            float sq = o0 * o0 + o1 * o1 + o2 * o2 + o3 * o3;
#pragma unroll
            for (int off = 16; off; off >>= 1) {
                s += __shfl_xor_sync(0xffffffffu, s, off);
                sq += __shfl_xor_sync(0xffffffffu, sq, off);
            }
            float mu = s * (1.0f / HD);
            float var = sq * (1.0f / HD) - mu * mu;
            float rstd = rsqrtf(var + 1e-5f);
            o0 = fmaxf((o0 - mu) * rstd * lng[col + 0] + lnb[col + 0], 0.0f);
            o1 = fmaxf((o1 - mu) * rstd * lng[col + 1] + lnb[col + 1], 0.0f);
            o2 = fmaxf((o2 - mu) * rstd * lng[col + 2] + lnb[col + 2], 0.0f);
            o3 = fmaxf((o3 - mu) * rstd * lng[col + 3] + lnb[col + 3], 0.0f);
            if (addres && grow < n) {
                const float4 hv = *(const float4*)&Out[grow * HD + col];
                o0 += hv.x; o1 += hv.y; o2 += hv.z; o3 += hv.w;
            }
        }
        if (grow < n) {
            float4 ov = make_float4(o0, o1, o2, o3);
            *(float4*)&Out[grow * HD + col] = ov;
        }
    }
}

// ---------------- readout ------------------------------------------------------
__global__ void pool_k(const float* __restrict__ h,
                       const int* __restrict__ batch,
                       float* __restrict__ pooled, float* __restrict__ cnt) {
    int nidx = blockIdx.x * 8 + (threadIdx.x >> 5);
    int lane = threadIdx.x & 31;
    if (nidx >= NN) return;
    int g = batch[nidx];
    float4 v = *(const float4*)&h[nidx * HD + lane * 4];
    float* p = &pooled[g * HD + lane * 4];
    atomicAdd(p + 0, v.x);
    atomicAdd(p + 1, v.y);
    atomicAdd(p + 2, v.z);
    atomicAdd(p + 3, v.w);
    if (lane == 0) atomicAdd(&cnt[g], 1.0f);
}

__global__ void readout_k(const float* __restrict__ pooled,
                          const float* __restrict__ cnt,
                          const float* __restrict__ w1, const float* __restrict__ b1,
                          const float* __restrict__ w2, const float* __restrict__ b2,
                          const float* __restrict__ w3, const float* __restrict__ b3,
                          float* __restrict__ out) {
    __shared__ float p[HD];
    __shared__ float o1s[HD];
    __shared__ float o2s[64];
    int g = blockIdx.x, c = threadIdx.x;
    float cc = fmaxf(cnt[g], 1.0f);
    p[c] = pooled[g * HD + c] / cc;
    __syncthreads();
    float acc = b1[c];
    for (int k = 0; k < HD; k++) acc += p[k] * w1[k * HD + c];
    o1s[c] = fmaxf(acc, 0.0f);
    __syncthreads();
    if (c < 64) {
        float a = b2[c];
        for (int k = 0; k < HD; k++) a += o1s[k] * w2[k * 64 + c];
        o2s[c] = fmaxf(a, 0.0f);
    }
    __syncthreads();
    if (c == 0) {
        float a = b3[0];
        for (int k = 0; k < 64; k++) a += o2s[k] * w3[k];
        out[g] = a;
    }
}

// ---------------- launch --------------------------------------------------------
extern "C" void kernel_launch(void* const* d_in, const int* in_sizes, int n_in,
                              void* d_out, int out_size) {
    const float* x       = (const float*)d_in[0];
    const int*   ei      = (const int*)d_in[1];
    const float* pos     = (const float*)d_in[3];
    const int*   batch   = (const int*)d_in[4];
    const float* enc_w   = (const float*)d_in[5];
    const float* enc_b   = (const float*)d_in[6];
    const float* msg_w1  = (const float*)d_in[9];
    const float* msg_b1  = (const float*)d_in[10];
    const float* msg_w2  = (const float*)d_in[11];
    const float* msg_b2  = (const float*)d_in[12];
    const float* upd_w1  = (const float*)d_in[13];
    const float* upd_b1  = (const float*)d_in[14];
    const float* upd_w2  = (const float*)d_in[15];
    const float* upd_b2  = (const float*)d_in[16];
    const float* ln_g    = (const float*)d_in[17];
    const float* ln_b    = (const float*)d_in[18];
    const float* mlp_w1  = (const float*)d_in[19];
    const float* mlp_b1  = (const float*)d_in[20];
    const float* mlp_w2  = (const float*)d_in[21];
    const float* mlp_b2  = (const float*)d_in[22];
    const float* mlp_w3  = (const float*)d_in[23];
    const float* mlp_b3  = (const float*)d_in[24];
    float*       out     = (float*)d_out;

    float *h, *P1, *P2, *Yagg, *T, *dist, *degf, *W2U, *cvec, *pooled, *cnt;
    cudaGetSymbolAddress((void**)&h, d_h);
    cudaGetSymbolAddress((void**)&P1, d_P1);
    cudaGetSymbolAddress((void**)&P2, d_P2);
    cudaGetSymbolAddress((void**)&Yagg, d_Yagg);
    cudaGetSymbolAddress((void**)&T, d_T);
    cudaGetSymbolAddress((void**)&dist, d_dist);
    cudaGetSymbolAddress((void**)&degf, d_degf);
    cudaGetSymbolAddress((void**)&W2U, d_W2U);
    cudaGetSymbolAddress((void**)&cvec, d_cvec);
    cudaGetSymbolAddress((void**)&pooled, d_pooled);
    cudaGetSymbolAddress((void**)&cnt, d_cnt);

    const int SM1 = (128 * HD + 128 * HD) * 4;   // 128 KB (single-A gemm)
    const int SM2 = (256 * HD + 128 * HD) * 4;   // 192 KB (two-A gemm)
    cudaFuncSetAttribute(gemm_k<0, false>, cudaFuncAttributeMaxDynamicSharedMemorySize, SM1);
    cudaFuncSetAttribute(gemm_k<1, false>, cudaFuncAttributeMaxDynamicSharedMemorySize, SM1);
    cudaFuncSetAttribute(gemm_k<2, true>,  cudaFuncAttributeMaxDynamicSharedMemorySize, SM2);
    cudaFuncSetAttribute(gemm_k<3, false>, cudaFuncAttributeMaxDynamicSharedMemorySize, SM1);

    const int GB = (NN + 127) / 128;  // 391 gemm blocks

    // prep
    zero_k<<<(NN + 255) / 256, 256>>>(degf, NN);
    zero_k<<<(NG * HD + 255) / 256, 256>>>(pooled, NG * HD);
    zero_k<<<1, 64>>>(cnt, NG);
    prep_edges<<<(EE + 255) / 256, 256>>>(ei, pos, dist, degf);
    encoder_k<<<(NN + 15) / 16, 128>>>(x, enc_w, enc_b, h);
    build_w2u<<<dim3(129, 4), 128>>>(msg_w2, msg_b2, upd_w1, W2U, cvec);

    for (int l = 0; l < NLAY; l++) {
        const float* w1l = msg_w1 + l * 257 * HD;
        zero_k<<<(NN * HD + 255) / 256, 256>>>(Yagg, NN * HD);
        // P1 = h@W1a + b1 ; P2 = h@W1b
        gemm_k<0, false><<<GB, 512, SM1>>>(h, nullptr, w1l, nullptr,
                                           msg_b1 + l * HD, nullptr, nullptr,
                                           nullptr, nullptr, 0, P1, NN);
        gemm_k<1, false><<<GB, 512, SM1>>>(h, nullptr, w1l + 128 * HD, nullptr,
                                           nullptr, nullptr, nullptr,
                                           nullptr, nullptr, 0, P2, NN);
        // scatter relu-messages
        edge_k<<<EE / 8, 256>>>(ei, dist, P1, P2, w1l + 256 * HD, Yagg);
        // T = relu(h@U1a + Yagg@W2U + deg*cvec + bu1)
        gemm_k<2, true><<<GB, 512, SM2>>>(h, Yagg, upd_w1 + l * 256 * HD,
                                          W2U + l * HD * HD, upd_b1 + l * HD,
                                          degf, cvec + l * HD,
                                          nullptr, nullptr, 0, T, NN);
        // h = (l? h : 0) + relu(LN(T@U2 + bu2))
        gemm_k<3, false><<<GB, 512, SM1>>>(T, nullptr, upd_w2 + l * HD * HD, nullptr,
                                           upd_b2 + l * HD, nullptr, nullptr,
                                           ln_g + l * HD, ln_b + l * HD,
                                           (l > 0) ? 1 : 0, h, NN);
    }

    pool_k<<<(NN + 7) / 8, 256>>>(h, batch, pooled, cnt);
    readout_k<<<NG, 128>>>(pooled, cnt, mlp_w1, mlp_b1, mlp_w2, mlp_b2,
                           mlp_w3, mlp_b3, out);
}

// round 4
// speedup vs baseline: 1.4558x; 1.4558x over previous
#include <cuda_runtime.h>

#define NN 50000
#define EE 500000
#define HD 128
#define NLAY 4
#define NG 64
#define NB 196  // (NN+255)/256 scan blocks

// ---------------- scratch (device globals) ------------------------------------
__device__ __align__(16) float d_h[NN * HD];
__device__ __align__(16) float d_P1[NN * HD];
__device__ __align__(16) float d_P2[NN * HD];
__device__ __align__(16) float d_Yagg[NN * HD];
__device__ __align__(16) float d_T[NN * HD];
__device__ __align__(16) float d_degf[NN];
__device__ __align__(16) float d_W2U[NLAY * HD * HD];
__device__ __align__(16) float d_cvec[NLAY * HD];
__device__ __align__(16) float d_pooled[NG * HD];
__device__ __align__(16) float d_cnt[NG];
// CSR
__device__ __align__(16) int   d_rowptr[NN + 1];
__device__ __align__(16) int   d_cursor[NN];
__device__ __align__(16) int   d_bsum[256];
__device__ __align__(16) int   d_esrc[EE];
__device__ __align__(16) float d_edist[EE];

// ---------------- f32x2 packed helpers ---------------------------------------
__device__ __forceinline__ unsigned long long pk2(float lo, float hi) {
    unsigned long long r;
    asm("mov.b64 %0, {%1,%2};" : "=l"(r) : "f"(lo), "f"(hi));
    return r;
}
__device__ __forceinline__ void upk2(unsigned long long v, float& lo, float& hi) {
    asm("mov.b64 {%0,%1}, %2;" : "=f"(lo), "=f"(hi) : "l"(v));
}
__device__ __forceinline__ unsigned long long fma2(unsigned long long a,
                                                   unsigned long long b,
                                                   unsigned long long c) {
    unsigned long long d;
    asm("fma.rn.f32x2 %0, %1, %2, %3;" : "=l"(d) : "l"(a), "l"(b), "l"(c));
    return d;
}

// ---------------- tiny utility kernels ----------------------------------------
__global__ void zero_k(float* __restrict__ p, int n) {
    int i = blockIdx.x * blockDim.x + threadIdx.x;
    if (i < n) p[i] = 0.0f;
}
__global__ void zero_int(int* __restrict__ p, int n) {
    int i = blockIdx.x * blockDim.x + threadIdx.x;
    if (i < n) p[i] = 0;
}

// ---------------- CSR build ----------------------------------------------------
__global__ void count_k(const int* __restrict__ ei, int* __restrict__ deg) {
    int e = blockIdx.x * blockDim.x + threadIdx.x;
    if (e < EE) atomicAdd(&deg[ei[EE + e]], 1);
}

__global__ void scan_part(const int* __restrict__ deg, int* __restrict__ rowptr,
                          int* __restrict__ bsum) {
    __shared__ int s[256];
    int tid = threadIdx.x;
    int i = blockIdx.x * 256 + tid;
    int v = (i < NN) ? deg[i] : 0;
    s[tid] = v;
    __syncthreads();
#pragma unroll
    for (int off = 1; off < 256; off <<= 1) {
        int t = (tid >= off) ? s[tid - off] : 0;
        __syncthreads();
        s[tid] += t;
        __syncthreads();
    }
    if (i < NN) rowptr[i] = s[tid] - v;   // block-local exclusive
    if (tid == 255) bsum[blockIdx.x] = s[255];
}

__global__ void scan_bsum(int* __restrict__ bsum) {
    __shared__ int s[256];
    int tid = threadIdx.x;
    int v = (tid < NB) ? bsum[tid] : 0;
    s[tid] = v;
    __syncthreads();
#pragma unroll
    for (int off = 1; off < 256; off <<= 1) {
        int t = (tid >= off) ? s[tid - off] : 0;
        __syncthreads();
        s[tid] += t;
        __syncthreads();
    }
    if (tid < NB) bsum[tid] = s[tid] - v; // exclusive
}

__global__ void add_off(int* __restrict__ rowptr, const int* __restrict__ bsum,
                        int* __restrict__ cursor) {
    int i = blockIdx.x * 256 + threadIdx.x;
    if (i < NN) {
        int r = rowptr[i] + bsum[blockIdx.x];
        rowptr[i] = r;
        cursor[i] = r;
    }
    if (i == 0) rowptr[NN] = EE;
}

__global__ void degf_k(const int* __restrict__ rowptr, float* __restrict__ degf) {
    int i = blockIdx.x * blockDim.x + threadIdx.x;
    if (i < NN) degf[i] = (float)(rowptr[i + 1] - rowptr[i]);
}

__global__ void scatter_k(const int* __restrict__ ei,
                          const float* __restrict__ pos,
                          int* __restrict__ cursor,
                          int* __restrict__ esrc,
                          float* __restrict__ edist) {
    int e = blockIdx.x * blockDim.x + threadIdx.x;
    if (e >= EE) return;
    int s = ei[e];
    int t = ei[EE + e];
    float dx = pos[t * 3 + 0] - pos[s * 3 + 0];
    float dy = pos[t * 3 + 1] - pos[s * 3 + 1];
    float dz = pos[t * 3 + 2] - pos[s * 3 + 2];
    float dd = sqrtf(dx * dx + dy * dy + dz * dz);
    int p = atomicAdd(&cursor[t], 1);
    esrc[p] = s;
    edist[p] = dd;
}

// ---------------- encoder: h = x @ enc_w + enc_b (K=15) -----------------------
__global__ void encoder_k(const float* __restrict__ x,
                          const float* __restrict__ w,
                          const float* __restrict__ b,
                          float* __restrict__ h) {
    __shared__ float ws[15 * HD];
    __shared__ float xs[16 * 15];
    __shared__ float bs[HD];
    int c = threadIdx.x;
    for (int i = c; i < 15 * HD; i += HD) ws[i] = w[i];
    bs[c] = b[c];
    int n0 = blockIdx.x * 16;
    for (int i = c; i < 16 * 15; i += HD) {
        int nn = i / 15, kk = i % 15;
        int g = n0 + nn;
        xs[i] = (g < NN) ? x[g * 15 + kk] : 0.0f;
    }
    __syncthreads();
    for (int r = 0; r < 16; r++) {
        int g = n0 + r;
        if (g >= NN) break;
        float acc = bs[c];
#pragma unroll
        for (int k = 0; k < 15; k++) acc += xs[r * 15 + k] * ws[k * HD + c];
        h[g * HD + c] = acc;
    }
}

// W2U[l] = msg_w2[l] @ U1b[l];  cvec[l] = msg_b2[l] @ U1b[l]
__global__ void build_w2u(const float* __restrict__ msg_w2,
                          const float* __restrict__ msg_b2,
                          const float* __restrict__ upd_w1,
                          float* __restrict__ W2U,
                          float* __restrict__ cvec) {
    int l = blockIdx.y, k = blockIdx.x, c = threadIdx.x;
    const float* u1b = upd_w1 + l * 256 * HD + 128 * HD;
    if (k < HD) {
        const float* wrow = msg_w2 + (l * HD + k) * HD;
        float acc = 0.0f;
        for (int j = 0; j < HD; j++) acc += wrow[j] * u1b[j * HD + c];
        W2U[(l * HD + k) * HD + c] = acc;
    } else {
        const float* brow = msg_b2 + l * HD;
        float acc = 0.0f;
        for (int j = 0; j < HD; j++) acc += brow[j] * u1b[j * HD + c];
        cvec[l * HD + c] = acc;
    }
}

// ---------------- CSR gather aggregation ---------------------------------------
// warp per node: Yagg[i] = sum_e relu(P1[i] + P2[src[e]] + dist[e]*w1c)
__global__ void __launch_bounds__(256) aggregate_k(
    const int* __restrict__ rowptr,
    const int* __restrict__ esrc,
    const float* __restrict__ edist,
    const float* __restrict__ P1,
    const float* __restrict__ P2,
    const float* __restrict__ w1c,
    float* __restrict__ Yagg) {
    int node = blockIdx.x * 8 + (threadIdx.x >> 5);
    int lane = threadIdx.x & 31;
    int c4 = lane * 4;
    const float4 cw = *(const float4*)&w1c[c4];
    const float4 p1 = *(const float4*)&P1[node * HD + c4];
    float a0 = 0.f, a1 = 0.f, a2 = 0.f, a3 = 0.f;
    int beg = rowptr[node], end = rowptr[node + 1];
    for (int e = beg; e < end; e++) {
        int s = esrc[e];
        float dd = edist[e];
        const float4 b = *(const float4*)&P2[s * HD + c4];
        a0 += fmaxf(p1.x + b.x + dd * cw.x, 0.0f);
        a1 += fmaxf(p1.y + b.y + dd * cw.y, 0.0f);
        a2 += fmaxf(p1.z + b.z + dd * cw.z, 0.0f);
        a3 += fmaxf(p1.w + b.w + dd * cw.w, 0.0f);
    }
    *(float4*)&Yagg[node * HD + c4] = make_float4(a0, a1, a2, a3);
}

// ---------------- main GEMM: 64 rows x 128 cols, 256 thr, 2 blocks/SM ----------
__device__ __forceinline__ void load_tile_A64(float* As, const float* __restrict__ A,
                                              int rowbase, int tid, int n) {
    const float4* av = (const float4*)A;
    float4* asv = (float4*)As;
#pragma unroll
    for (int i = 0; i < 8; i++) {
        int idx = tid + i * 256;          // 0..2047
        int r = idx >> 5;
        int grow = rowbase + r;
        int cr = (grow < n) ? grow : (n - 1);
        asv[idx] = av[cr * 32 + (idx & 31)];
    }
}

__device__ __forceinline__ void load_tile_B(float* Bs, const float* __restrict__ B,
                                            int tid) {
    const float4* bv = (const float4*)B;
    float4* bs = (float4*)Bs;
#pragma unroll
    for (int i = 0; i < 16; i++) bs[tid + i * 256] = bv[tid + i * 256];
}

__device__ __forceinline__ void gemm_compute(const float* As, const float* Bs,
                                             unsigned long long acc0[8],
                                             unsigned long long acc1[8],
                                             int warp, int lane) {
#pragma unroll 2
    for (int k0 = 0; k0 < HD; k0 += 4) {
        float4 avv[8];
#pragma unroll
        for (int r = 0; r < 8; r++)
            avv[r] = *(const float4*)&As[(warp * 8 + r) * HD + k0];
#pragma unroll
        for (int kk = 0; kk < 4; kk++) {
            const unsigned long long* bp =
                (const unsigned long long*)&Bs[(k0 + kk) * HD + lane * 4];
            unsigned long long b01 = bp[0];
            unsigned long long b23 = bp[1];
#pragma unroll
            for (int r = 0; r < 8; r++) {
                float a = (&avv[r].x)[kk];
                unsigned long long a2 = pk2(a, a);
                acc0[r] = fma2(a2, b01, acc0[r]);
                acc1[r] = fma2(a2, b23, acc1[r]);
            }
        }
    }
}

// EPI: 0 = +bias, 1 = plain, 2 = +deg*cvec+bias, relu, 3 = +bias, LN, relu, (+res)
template <int EPI, bool TWOA>
__global__ void __launch_bounds__(256) gemm_k(
    const float* __restrict__ A0, const float* __restrict__ A1,
    const float* __restrict__ B0, const float* __restrict__ B1,
    const float* __restrict__ bias,
    const float* __restrict__ degf, const float* __restrict__ cvec,
    const float* __restrict__ lng, const float* __restrict__ lnb,
    int addres, float* __restrict__ Out, int n) {
    extern __shared__ float sm[];
    float* Bs = sm;                 // 128 x 128
    float* As = sm + 128 * HD;      // 64 x 128
    int tid = threadIdx.x;
    int rowbase = blockIdx.x * 64;

    load_tile_B(Bs, B0, tid);
    load_tile_A64(As, A0, rowbase, tid, n);
    __syncthreads();

    unsigned long long acc0[8], acc1[8];
#pragma unroll
    for (int r = 0; r < 8; r++) { acc0[r] = 0ULL; acc1[r] = 0ULL; }

    int warp = tid >> 5, lane = tid & 31;
    gemm_compute(As, Bs, acc0, acc1, warp, lane);
    if (TWOA) {
        __syncthreads();
        load_tile_B(Bs, B1, tid);
        load_tile_A64(As, A1, rowbase, tid, n);
        __syncthreads();
        gemm_compute(As, Bs, acc0, acc1, warp, lane);
    }

    int col = lane * 4;
    int rb = rowbase + warp * 8;
#pragma unroll
    for (int r = 0; r < 8; r++) {
        int grow = rb + r;
        float o0, o1, o2, o3;
        upk2(acc0[r], o0, o1);
        upk2(acc1[r], o2, o3);
        if (EPI == 0) {
            o0 += bias[col + 0]; o1 += bias[col + 1];
            o2 += bias[col + 2]; o3 += bias[col + 3];
        }
        if (EPI == 2) {
            float dg = degf[(grow < n) ? grow : 0];
            o0 = fmaxf(o0 + dg * cvec[col + 0] + bias[col + 0], 0.0f);
            o1 = fmaxf(o1 + dg * cvec[col + 1] + bias[col + 1], 0.0f);
            o2 = fmaxf(o2 + dg * cvec[col + 2] + bias[col + 2], 0.0f);
            o3 = fmaxf(o3 + dg * cvec[col + 3] + bias[col + 3], 0.0f);
        }
        if (EPI == 3) {
            o0 += bias[col + 0]; o1 += bias[col + 1];
            o2 += bias[col + 2]; o3 += bias[col + 3];
            float s = o0 + o1 + o2 + o3;
            float sq = o0 * o0 + o1 * o1 + o2 * o2 + o3 * o3;
#pragma unroll
            for (int off = 16; off; off >>= 1) {
                s += __shfl_xor_sync(0xffffffffu, s, off);
                sq += __shfl_xor_sync(0xffffffffu, sq, off);
            }
            float mu = s * (1.0f / HD);
            float var = sq * (1.0f / HD) - mu * mu;
            float rstd = rsqrtf(var + 1e-5f);
            o0 = fmaxf((o0 - mu) * rstd * lng[col + 0] + lnb[col + 0], 0.0f);
            o1 = fmaxf((o1 - mu) * rstd * lng[col + 1] + lnb[col + 1], 0.0f);
            o2 = fmaxf((o2 - mu) * rstd * lng[col + 2] + lnb[col + 2], 0.0f);
            o3 = fmaxf((o3 - mu) * rstd * lng[col + 3] + lnb[col + 3], 0.0f);
            if (addres && grow < n) {
                const float4 hv = *(const float4*)&Out[grow * HD + col];
                o0 += hv.x; o1 += hv.y; o2 += hv.z; o3 += hv.w;
            }
        }
        if (grow < n) {
            *(float4*)&Out[grow * HD + col] = make_float4(o0, o1, o2, o3);
        }
    }
}

// ---------------- readout ------------------------------------------------------
__global__ void pool_k(const float* __restrict__ h,
                       const int* __restrict__ batch,
                       float* __restrict__ pooled, float* __restrict__ cnt) {
    int nidx = blockIdx.x * 8 + (threadIdx.x >> 5);
    int lane = threadIdx.x & 31;
    if (nidx >= NN) return;
    int g = batch[nidx];
    float4 v = *(const float4*)&h[nidx * HD + lane * 4];
    float* p = &pooled[g * HD + lane * 4];
    atomicAdd(p + 0, v.x);
    atomicAdd(p + 1, v.y);
    atomicAdd(p + 2, v.z);
    atomicAdd(p + 3, v.w);
    if (lane == 0) atomicAdd(&cnt[g], 1.0f);
}

__global__ void readout_k(const float* __restrict__ pooled,
                          const float* __restrict__ cnt,
                          const float* __restrict__ w1, const float* __restrict__ b1,
                          const float* __restrict__ w2, const float* __restrict__ b2,
                          const float* __restrict__ w3, const float* __restrict__ b3,
                          float* __restrict__ out) {
    __shared__ float p[HD];
    __shared__ float o1s[HD];
    __shared__ float o2s[64];
    int g = blockIdx.x, c = threadIdx.x;
    float cc = fmaxf(cnt[g], 1.0f);
    p[c] = pooled[g * HD + c] / cc;
    __syncthreads();
    float acc = b1[c];
    for (int k = 0; k < HD; k++) acc += p[k] * w1[k * HD + c];
    o1s[c] = fmaxf(acc, 0.0f);
    __syncthreads();
    if (c < 64) {
        float a = b2[c];
        for (int k = 0; k < HD; k++) a += o1s[k] * w2[k * 64 + c];
        o2s[c] = fmaxf(a, 0.0f);
    }
    __syncthreads();
    if (c == 0) {
        float a = b3[0];
        for (int k = 0; k < 64; k++) a += o2s[k] * w3[k];
        out[g] = a;
    }
}

// ---------------- launch --------------------------------------------------------
extern "C" void kernel_launch(void* const* d_in, const int* in_sizes, int n_in,
                              void* d_out, int out_size) {
    const float* x       = (const float*)d_in[0];
    const int*   ei      = (const int*)d_in[1];
    const float* pos     = (const float*)d_in[3];
    const int*   batch   = (const int*)d_in[4];
    const float* enc_w   = (const float*)d_in[5];
    const float* enc_b   = (const float*)d_in[6];
    const float* msg_w1  = (const float*)d_in[9];
    const float* msg_b1  = (const float*)d_in[10];
    const float* msg_w2  = (const float*)d_in[11];
    const float* msg_b2  = (const float*)d_in[12];
    const float* upd_w1  = (const float*)d_in[13];
    const float* upd_b1  = (const float*)d_in[14];
    const float* upd_w2  = (const float*)d_in[15];
    const float* upd_b2  = (const float*)d_in[16];
    const float* ln_g    = (const float*)d_in[17];
    const float* ln_b    = (const float*)d_in[18];
    const float* mlp_w1  = (const float*)d_in[19];
    const float* mlp_b1  = (const float*)d_in[20];
    const float* mlp_w2  = (const float*)d_in[21];
    const float* mlp_b2  = (const float*)d_in[22];
    const float* mlp_w3  = (const float*)d_in[23];
    const float* mlp_b3  = (const float*)d_in[24];
    float*       out     = (float*)d_out;

    float *h, *P1, *P2, *Yagg, *T, *degf, *W2U, *cvec, *pooled, *cnt, *edist;
    int *rowptr, *cursor, *bsum, *esrc;
    cudaGetSymbolAddress((void**)&h, d_h);
    cudaGetSymbolAddress((void**)&P1, d_P1);
    cudaGetSymbolAddress((void**)&P2, d_P2);
    cudaGetSymbolAddress((void**)&Yagg, d_Yagg);
    cudaGetSymbolAddress((void**)&T, d_T);
    cudaGetSymbolAddress((void**)&degf, d_degf);
    cudaGetSymbolAddress((void**)&W2U, d_W2U);
    cudaGetSymbolAddress((void**)&cvec, d_cvec);
    cudaGetSymbolAddress((void**)&pooled, d_pooled);
    cudaGetSymbolAddress((void**)&cnt, d_cnt);
    cudaGetSymbolAddress((void**)&rowptr, d_rowptr);
    cudaGetSymbolAddress((void**)&cursor, d_cursor);
    cudaGetSymbolAddress((void**)&bsum, d_bsum);
    cudaGetSymbolAddress((void**)&esrc, d_esrc);
    cudaGetSymbolAddress((void**)&edist, d_edist);

    const int SMEM = (128 * HD + 64 * HD) * 4;   // 96 KB
    cudaFuncSetAttribute(gemm_k<0, false>, cudaFuncAttributeMaxDynamicSharedMemorySize, SMEM);
    cudaFuncSetAttribute(gemm_k<1, false>, cudaFuncAttributeMaxDynamicSharedMemorySize, SMEM);
    cudaFuncSetAttribute(gemm_k<2, true>,  cudaFuncAttributeMaxDynamicSharedMemorySize, SMEM);
    cudaFuncSetAttribute(gemm_k<3, false>, cudaFuncAttributeMaxDynamicSharedMemorySize, SMEM);

    const int GB = (NN + 63) / 64;   // 782 blocks

    // ---- CSR build + prep ----
    zero_int<<<(NN + 255) / 256, 256>>>(cursor, NN);           // cursor = deg counts
    count_k<<<(EE + 255) / 256, 256>>>(ei, cursor);
    scan_part<<<NB, 256>>>(cursor, rowptr, bsum);
    scan_bsum<<<1, 256>>>(bsum);
    add_off<<<NB, 256>>>(rowptr, bsum, cursor);
    degf_k<<<(NN + 255) / 256, 256>>>(rowptr, degf);
    scatter_k<<<(EE + 255) / 256, 256>>>(ei, pos, cursor, esrc, edist);

    zero_k<<<(NG * HD + 255) / 256, 256>>>(pooled, NG * HD);
    zero_k<<<1, 64>>>(cnt, NG);
    encoder_k<<<(NN + 15) / 16, 128>>>(x, enc_w, enc_b, h);
    build_w2u<<<dim3(129, 4), 128>>>(msg_w2, msg_b2, upd_w1, W2U, cvec);

    for (int l = 0; l < NLAY; l++) {
        const float* w1l = msg_w1 + l * 257 * HD;
        // P1 = h@W1a + b1 ; P2 = h@W1b
        gemm_k<0, false><<<GB, 256, SMEM>>>(h, nullptr, w1l, nullptr,
                                            msg_b1 + l * HD, nullptr, nullptr,
                                            nullptr, nullptr, 0, P1, NN);
        gemm_k<1, false><<<GB, 256, SMEM>>>(h, nullptr, w1l + 128 * HD, nullptr,
                                            nullptr, nullptr, nullptr,
                                            nullptr, nullptr, 0, P2, NN);
        // CSR gather: Yagg[i] = sum_e relu(P1[i]+P2[src]+dist*w1c)
        aggregate_k<<<NN / 8, 256>>>(rowptr, esrc, edist, P1, P2,
                                     w1l + 256 * HD, Yagg);
        // T = relu(h@U1a + Yagg@W2U + deg*cvec + bu1)
        gemm_k<2, true><<<GB, 256, SMEM>>>(h, Yagg, upd_w1 + l * 256 * HD,
                                           W2U + l * HD * HD, upd_b1 + l * HD,
                                           degf, cvec + l * HD,
                                           nullptr, nullptr, 0, T, NN);
        // h = (l? h : 0) + relu(LN(T@U2 + bu2))
        gemm_k<3, false><<<GB, 256, SMEM>>>(T, nullptr, upd_w2 + l * HD * HD, nullptr,
                                            upd_b2 + l * HD, nullptr, nullptr,
                                            ln_g + l * HD, ln_b + l * HD,
                                            (l > 0) ? 1 : 0, h, NN);
    }

    pool_k<<<(NN + 7) / 8, 256>>>(h, batch, pooled, cnt);
    readout_k<<<NG, 128>>>(pooled, cnt, mlp_w1, mlp_b1, mlp_w2, mlp_b2,
                           mlp_w3, mlp_b3, out);
}